// round 2
// baseline (speedup 1.0000x reference)
#include <cuda_runtime.h>

// ---------------- problem constants ----------------
#define S_    2048
#define LMAX  16
#define DW    256      // word emb dim
#define DC    64       // char emb dim
#define HC    256      // char hidden
#define HW    512      // word hidden
#define GW    2048     // 4*HW
#define TT    64       // tags
#define KC    320      // DC + HC
#define WCTA  64       // word-lstm CTAs

// ---------------- device scratch (no allocs allowed) ----------------
__device__ float g_WcT[KC * HC * 4];          // [k][j][gate] char weights (ih|hh stacked on k)
__device__ float g_WtT[HW * TT];              // [k][tag] transposed W_tag
__device__ float g_win[S_ * HW];              // [S][512] concat(word_emb, h_char)
__device__ float g_Gw[(size_t)S_ * GW];       // [S][2048] ih-gates + bias
__device__ float g_hs[(size_t)S_ * HW];       // [S][512] word-lstm outputs
__device__ float g_hbuf[2 * HW];              // double-buffered h broadcast
__device__ volatile unsigned g_wstep[WCTA];   // per-CTA step counters

// ---------------- helpers ----------------
__device__ __forceinline__ unsigned long long pk2(float a, float b) {
    unsigned long long r;
    asm("mov.b64 %0, {%1, %2};" : "=l"(r) : "f"(a), "f"(b));
    return r;
}
__device__ __forceinline__ void up2(unsigned long long v, float& a, float& b) {
    asm("mov.b64 {%0, %1}, %2;" : "=f"(a), "=f"(b) : "l"(v));
}
__device__ __forceinline__ void fma2(unsigned long long& d, unsigned long long a, unsigned long long b) {
    asm("fma.rn.f32x2 %0, %1, %2, %0;" : "+l"(d) : "l"(a), "l"(b));
}
__device__ __forceinline__ float sigf(float x)   { return 1.0f / (1.0f + __expf(-x)); }
__device__ __forceinline__ float tanhf_(float x) { return 2.0f / (1.0f + __expf(-2.0f * x)) - 1.0f; }

// ================= kernel 0: prep =================
#define N_WC   (KC * HC * 4)          // 327680
#define N_WT   (HW * TT)              // 32768
#define N_WIN  (S_ * DW)              // 524288
#define N_PREP (N_WC + N_WT + N_WIN + 2 * HW + WCTA)

__global__ void k_prep(const float* __restrict__ Wcih, const float* __restrict__ Wchh,
                       const float* __restrict__ Wtag, const float* __restrict__ wemb,
                       const int* __restrict__ wixs)
{
    long long i = (long long)blockIdx.x * 256 + threadIdx.x;
    if (i < N_WC) {
        int k = (int)(i >> 10);           // i / 1024
        int rem = (int)(i & 1023);
        int j = rem >> 2, g = rem & 3;
        int row = g * HC + j;
        g_WcT[i] = (k < DC) ? Wcih[(size_t)row * DC + k]
                            : Wchh[(size_t)row * HC + (k - DC)];
        return;
    }
    i -= N_WC;
    if (i < N_WT) {
        int k = (int)(i >> 6), t = (int)(i & 63);
        g_WtT[i] = Wtag[(size_t)t * HW + k];
        return;
    }
    i -= N_WT;
    if (i < N_WIN) {
        int s = (int)(i >> 8), d = (int)(i & 255);
        g_win[(size_t)s * HW + d] = wemb[(size_t)wixs[s] * DW + d];
        return;
    }
    i -= N_WIN;
    if (i < 2 * HW) { g_hbuf[i] = 0.0f; return; }
    i -= 2 * HW;
    if (i < WCTA) g_wstep[i] = 0u;
}

// ================= kernel 1: char LSTM (16 words / CTA) =================
__global__ __launch_bounds__(256, 1)
void k_char(const int* __restrict__ cix, const int* __restrict__ clen,
            const float* __restrict__ cemb,
            const float* __restrict__ bcih, const float* __restrict__ bchh)
{
    __shared__ __align__(16) float xT[DC * 18];   // [k][word], padded row 18
    __shared__ __align__(16) float hT[HC * 18];
    const int j  = threadIdx.x;                   // hidden unit
    const int w0 = blockIdx.x * 16;

    float bi[4];
#pragma unroll
    for (int g = 0; g < 4; g++) bi[g] = bcih[g * HC + j] + bchh[g * HC + j];

    int len[16];
#pragma unroll
    for (int w = 0; w < 16; w++) len[w] = clen[w0 + w];

    float c[16];
#pragma unroll
    for (int w = 0; w < 16; w++) c[w] = 0.0f;

    for (int i = j; i < HC * 18; i += 256) hT[i] = 0.0f;
    // stage x for t=0
    for (int i = j; i < 1024; i += 256) {
        int w = i >> 6, k = i & 63;
        xT[k * 18 + w] = cemb[(size_t)cix[(w0 + w) * LMAX + 0] * DC + k];
    }

    for (int t = 0; t < LMAX; t++) {
        __syncthreads();   // hT/xT writes visible

        unsigned long long acc[4][8];
#pragma unroll
        for (int g = 0; g < 4; g++) {
            unsigned long long bp = pk2(bi[g], bi[g]);
#pragma unroll
            for (int p = 0; p < 8; p++) acc[g][p] = bp;
        }

        // K over x (0..63)
        for (int k = 0; k < DC; k++) {
            float4 wv = ((const float4*)g_WcT)[k * HC + j];
            const unsigned long long* xr = (const unsigned long long*)(xT + k * 18);
            unsigned long long wp0 = pk2(wv.x, wv.x), wp1 = pk2(wv.y, wv.y);
            unsigned long long wp2 = pk2(wv.z, wv.z), wp3 = pk2(wv.w, wv.w);
#pragma unroll
            for (int p = 0; p < 8; p++) {
                unsigned long long xp = xr[p];
                fma2(acc[0][p], wp0, xp); fma2(acc[1][p], wp1, xp);
                fma2(acc[2][p], wp2, xp); fma2(acc[3][p], wp3, xp);
            }
        }
        // K over h (0..255)
        for (int k = 0; k < HC; k++) {
            float4 wv = ((const float4*)g_WcT)[(DC + k) * HC + j];
            const unsigned long long* xr = (const unsigned long long*)(hT + k * 18);
            unsigned long long wp0 = pk2(wv.x, wv.x), wp1 = pk2(wv.y, wv.y);
            unsigned long long wp2 = pk2(wv.z, wv.z), wp3 = pk2(wv.w, wv.w);
#pragma unroll
            for (int p = 0; p < 8; p++) {
                unsigned long long xp = xr[p];
                fma2(acc[0][p], wp0, xp); fma2(acc[1][p], wp1, xp);
                fma2(acc[2][p], wp2, xp); fma2(acc[3][p], wp3, xp);
            }
        }

        __syncthreads();   // all reads of hT/xT done

        // epilogue: update c / h (frozen past word length)
#pragma unroll
        for (int p = 0; p < 8; p++) {
            float i0, i1, f0, f1, gg0, gg1, o0, o1;
            up2(acc[0][p], i0, i1); up2(acc[1][p], f0, f1);
            up2(acc[2][p], gg0, gg1); up2(acc[3][p], o0, o1);
            int w = 2 * p;
            if (t < len[w]) {
                c[w] = sigf(f0) * c[w] + sigf(i0) * tanhf_(gg0);
                hT[j * 18 + w] = sigf(o0) * tanhf_(c[w]);
            }
            w = 2 * p + 1;
            if (t < len[w]) {
                c[w] = sigf(f1) * c[w] + sigf(i1) * tanhf_(gg1);
                hT[j * 18 + w] = sigf(o1) * tanhf_(c[w]);
            }
        }
        // stage x for next step
        if (t + 1 < LMAX) {
            for (int i = j; i < 1024; i += 256) {
                int w = i >> 6, k = i & 63;
                xT[k * 18 + w] = cemb[(size_t)cix[(w0 + w) * LMAX + (t + 1)] * DC + k];
            }
        }
    }
    __syncthreads();
#pragma unroll
    for (int w = 0; w < 16; w++)
        g_win[(size_t)(w0 + w) * HW + DW + j] = hT[j * 18 + w];
}

// ================= kernel 2: word-input GEMM: Gw = win @ Wwih^T + bw =================
__global__ __launch_bounds__(256, 1)
void k_gemm(const float* __restrict__ Wwih,
            const float* __restrict__ bwih, const float* __restrict__ bwhh)
{
    __shared__ __align__(16) float As[32 * 132];
    __shared__ __align__(16) float Bs[32 * 132];
    const int tid = threadIdx.x;
    const int tx = tid & 15, ty = tid >> 4;
    const int sbase = blockIdx.y * 128, rbase = blockIdx.x * 128;

    unsigned long long acc[8][4];
#pragma unroll
    for (int i = 0; i < 8; i++)
#pragma unroll
        for (int p = 0; p < 4; p++) acc[i][p] = pk2(0.0f, 0.0f);

    for (int kt = 0; kt < HW; kt += 32) {
        __syncthreads();
#pragma unroll
        for (int q = 0; q < 4; q++) {
            int idx = tid + 256 * q;          // 0..1023
            int sr = idx >> 3, f = idx & 7;
            float4 av = *(const float4*)(g_win + (size_t)(sbase + sr) * HW + kt + f * 4);
            As[(f * 4 + 0) * 132 + sr] = av.x;
            As[(f * 4 + 1) * 132 + sr] = av.y;
            As[(f * 4 + 2) * 132 + sr] = av.z;
            As[(f * 4 + 3) * 132 + sr] = av.w;
            float4 bv = *(const float4*)(Wwih + (size_t)(rbase + sr) * HW + kt + f * 4);
            Bs[(f * 4 + 0) * 132 + sr] = bv.x;
            Bs[(f * 4 + 1) * 132 + sr] = bv.y;
            Bs[(f * 4 + 2) * 132 + sr] = bv.z;
            Bs[(f * 4 + 3) * 132 + sr] = bv.w;
        }
        __syncthreads();
#pragma unroll
        for (int k = 0; k < 32; k++) {
            const float* ar = As + k * 132 + ty * 8;
            float4 a0 = *(const float4*)ar;
            float4 a1 = *(const float4*)(ar + 4);
            const unsigned long long* br = (const unsigned long long*)(Bs + k * 132 + tx * 8);
            unsigned long long b0 = br[0], b1 = br[1], b2 = br[2], b3 = br[3];
            float a[8] = {a0.x, a0.y, a0.z, a0.w, a1.x, a1.y, a1.z, a1.w};
#pragma unroll
            for (int i = 0; i < 8; i++) {
                unsigned long long ap = pk2(a[i], a[i]);
                fma2(acc[i][0], ap, b0); fma2(acc[i][1], ap, b1);
                fma2(acc[i][2], ap, b2); fma2(acc[i][3], ap, b3);
            }
        }
    }
#pragma unroll
    for (int i = 0; i < 8; i++) {
        int srow = sbase + ty * 8 + i;
#pragma unroll
        for (int pq = 0; pq < 4; pq++) {
            float lo, hi; up2(acc[i][pq], lo, hi);
            int rcol = rbase + tx * 8 + 2 * pq;
            lo += bwih[rcol] + bwhh[rcol];
            hi += bwih[rcol + 1] + bwhh[rcol + 1];
            *(float2*)(g_Gw + (size_t)srow * GW + rcol) = make_float2(lo, hi);
        }
    }
}

// ================= kernel 3: word LSTM (persistent, 64 CTAs, Whh in registers) ===========
__global__ __launch_bounds__(256, 1)
void k_word(const float* __restrict__ Whh)
{
    __shared__ __align__(16) float sh[HW];
    const int tid = threadIdx.x, b = blockIdx.x;
    const int p = tid & 7;             // part of a row (8 parts x 64 weights)
    const int r_local = tid >> 3;      // 0..31
    const int j_local = r_local >> 2;  // 0..7
    const int gate = r_local & 3;      // 0..3 (i,f,g,o)
    const int lane = tid & 31;
    const int grow = gate * HW + b * 8 + j_local;
    const int jglob = b * 8 + j_local;

    // load my 64 weights into registers, packed as f32x2 pairs
    unsigned long long wpk[32];
    {
        const float4* wsrc = (const float4*)(Whh + (size_t)grow * HW + p * 64);
#pragma unroll
        for (int q = 0; q < 16; q++) {
            float4 v = wsrc[q];
            wpk[2 * q]     = pk2(v.x, v.y);
            wpk[2 * q + 1] = pk2(v.z, v.w);
        }
    }

    float cst = 0.0f;   // cell state, valid on lane 0 of each warp

    for (int s = 0; s < S_; s++) {
        if (s > 0) {
            if (tid < WCTA) { while (g_wstep[tid] < (unsigned)s) { } }
            __syncthreads();
        }
        {   // broadcast h into smem (bypass L1 via volatile)
            const volatile float* hb = g_hbuf + (s & 1) * HW;
            sh[tid] = hb[tid];
            sh[tid + 256] = hb[tid + 256];
        }
        __syncthreads();

        unsigned long long a0 = pk2(0.f, 0.f), a1 = a0, a2 = a0, a3 = a0;
        const ulonglong2* hr2 = (const ulonglong2*)(sh + p * 64);
#pragma unroll
        for (int q = 0; q < 16; q += 2) {
            ulonglong2 h0 = hr2[q];
            ulonglong2 h1 = hr2[q + 1];
            fma2(a0, wpk[2 * q],     h0.x);
            fma2(a1, wpk[2 * q + 1], h0.y);
            fma2(a2, wpk[2 * q + 2], h1.x);
            fma2(a3, wpk[2 * q + 3], h1.y);
        }
        fma2(a0, pk2(1.f, 1.f), a1);   // cheap combine (a0 += a1*1)
        fma2(a2, pk2(1.f, 1.f), a3);
        float l0, h0f, l2, h2f;
        up2(a0, l0, h0f); up2(a2, l2, h2f);
        float sum = (l0 + h0f) + (l2 + h2f);
        sum += __shfl_down_sync(0xffffffffu, sum, 4);
        sum += __shfl_down_sync(0xffffffffu, sum, 2);
        sum += __shfl_down_sync(0xffffffffu, sum, 1);

        float gval = 0.0f;
        if (p == 0) gval = sum + g_Gw[(size_t)s * GW + grow];
        // lanes 0,8,16,24 of each warp hold gates i,f,g,o of that warp's unit
        float iv = __shfl_sync(0xffffffffu, gval, 0);
        float fv = __shfl_sync(0xffffffffu, gval, 8);
        float gv = __shfl_sync(0xffffffffu, gval, 16);
        float ov = __shfl_sync(0xffffffffu, gval, 24);

        if (lane == 0) {
            cst = sigf(fv) * cst + sigf(iv) * tanhf_(gv);
            float h = sigf(ov) * tanhf_(cst);
            g_hbuf[((s + 1) & 1) * HW + jglob] = h;
            g_hs[(size_t)s * HW + jglob] = h;
            __threadfence();
        }
        __syncthreads();
        if (tid == 0) g_wstep[b] = (unsigned)(s + 1);
    }
}

// ================= kernel 4: tag projection + log-softmax =================
__global__ __launch_bounds__(64, 8)
void k_tag(const float* __restrict__ btag, float* __restrict__ out)
{
    __shared__ __align__(16) float sh[HW];
    __shared__ float red[2];
    const int s = blockIdx.x, t = threadIdx.x;

#pragma unroll
    for (int q = 0; q < 8; q++)
        sh[t + q * 64] = g_hs[(size_t)s * HW + t + q * 64];
    __syncthreads();

    float acc = btag[t];
#pragma unroll 8
    for (int k = 0; k < HW; k++) acc += sh[k] * g_WtT[k * TT + t];

    // log-softmax over 64 lanes (2 warps)
    float m = acc;
#pragma unroll
    for (int d = 16; d > 0; d >>= 1) m = fmaxf(m, __shfl_xor_sync(0xffffffffu, m, d));
    if ((t & 31) == 0) red[t >> 5] = m;
    __syncthreads();
    m = fmaxf(red[0], red[1]);
    __syncthreads();

    float e = expf(acc - m);
    float ss = e;
#pragma unroll
    for (int d = 16; d > 0; d >>= 1) ss += __shfl_xor_sync(0xffffffffu, ss, d);
    if ((t & 31) == 0) red[t >> 5] = ss;
    __syncthreads();
    ss = red[0] + red[1];

    out[s * TT + t] = acc - m - logf(ss);
}

// ================= launch =================
extern "C" void kernel_launch(void* const* d_in, const int* in_sizes, int n_in,
                              void* d_out, int out_size)
{
    const int*   word_ixs = (const int*)d_in[0];
    const int*   char_ixs = (const int*)d_in[1];
    const int*   char_len = (const int*)d_in[2];
    const float* word_emb = (const float*)d_in[3];
    const float* char_emb = (const float*)d_in[4];
    const float* Wc_ih    = (const float*)d_in[5];
    const float* Wc_hh    = (const float*)d_in[6];
    const float* bc_ih    = (const float*)d_in[7];
    const float* bc_hh    = (const float*)d_in[8];
    const float* Ww_ih    = (const float*)d_in[9];
    const float* Ww_hh    = (const float*)d_in[10];
    const float* bw_ih    = (const float*)d_in[11];
    const float* bw_hh    = (const float*)d_in[12];
    const float* W_tag    = (const float*)d_in[13];
    const float* b_tag    = (const float*)d_in[14];
    float* out = (float*)d_out;

    k_prep<<<(N_PREP + 255) / 256, 256>>>(Wc_ih, Wc_hh, W_tag, word_emb, word_ixs);
    k_char<<<S_ / 16, 256>>>(char_ixs, char_len, char_emb, bc_ih, bc_hh);
    k_gemm<<<dim3(GW / 128, S_ / 128), 256>>>(Ww_ih, bw_ih, bw_hh);
    k_word<<<WCTA, 256>>>(Ww_hh);
    k_tag<<<S_, 64>>>(b_tag, out);
}

// round 3
// speedup vs baseline: 1.1797x; 1.1797x over previous
#include <cuda_runtime.h>

// ---------------- problem constants ----------------
#define S_    2048
#define LMAX  16
#define DW    256      // word emb dim
#define DC    64       // char emb dim
#define HC    256      // char hidden
#define HW    512      // word hidden
#define GW    2048     // 4*HW
#define TT    64       // tags
#define KC    320      // DC + HC
#define WCTA  64       // word-lstm CTAs

// ---------------- device scratch (no allocs allowed) ----------------
__device__ float g_WcT[KC * HC * 4];             // [k][j][gate] char weights (ih|hh stacked on k)
__device__ float g_WtT[HW * TT];                 // [k][tag] transposed W_tag
__device__ float g_win[S_ * HW];                 // [S][512] concat(word_emb, h_char)
__device__ float g_Gw[(size_t)S_ * GW];          // [S][2048] ih-gates + bias
__device__ float g_hs[(size_t)S_ * HW];          // [S][512] word-lstm outputs
__device__ unsigned long long g_hpk[2 * HW];     // tagged h, double-buffered by step parity

// ---------------- helpers ----------------
__device__ __forceinline__ unsigned long long pk2(float a, float b) {
    unsigned long long r;
    asm("mov.b64 %0, {%1, %2};" : "=l"(r) : "f"(a), "f"(b));
    return r;
}
__device__ __forceinline__ void up2(unsigned long long v, float& a, float& b) {
    asm("mov.b64 {%0, %1}, %2;" : "=f"(a), "=f"(b) : "l"(v));
}
__device__ __forceinline__ void fma2(unsigned long long& d, unsigned long long a, unsigned long long b) {
    asm("fma.rn.f32x2 %0, %1, %2, %0;" : "+l"(d) : "l"(a), "l"(b));
}
__device__ __forceinline__ float sigf(float x)   { return 1.0f / (1.0f + __expf(-x)); }
__device__ __forceinline__ float tanhf_(float x) { return 2.0f / (1.0f + __expf(-2.0f * x)) - 1.0f; }

// tagged dataflow: {lo32 = h bits, hi32 = step tag}, relaxed gpu-scope (L2-coherent, no fences)
__device__ __forceinline__ unsigned long long ldtag(const unsigned long long* p) {
    unsigned long long v;
    asm volatile("ld.relaxed.gpu.global.u64 %0, [%1];" : "=l"(v) : "l"(p));
    return v;
}
__device__ __forceinline__ void sttag(unsigned long long* p, unsigned long long v) {
    asm volatile("st.relaxed.gpu.global.u64 [%0], %1;" : : "l"(p), "l"(v));
}
__device__ __forceinline__ unsigned long long pktag(float h, unsigned tag) {
    unsigned long long r;
    asm("mov.b64 %0, {%1, %2};" : "=l"(r) : "r"(__float_as_uint(h)), "r"(tag));
    return r;
}

// ================= kernel 0: prep =================
#define N_WC   (KC * HC * 4)          // 327680
#define N_WT   (HW * TT)              // 32768
#define N_WIN  (S_ * DW)              // 524288
#define N_HPK  (2 * HW)               // 1024
#define N_PREP (N_WC + N_WT + N_WIN + N_HPK)

__global__ void k_prep(const float* __restrict__ Wcih, const float* __restrict__ Wchh,
                       const float* __restrict__ Wtag, const float* __restrict__ wemb,
                       const int* __restrict__ wixs)
{
    long long i = (long long)blockIdx.x * 256 + threadIdx.x;
    if (i < N_WC) {
        int k = (int)(i >> 10);           // i / 1024
        int rem = (int)(i & 1023);
        int j = rem >> 2, g = rem & 3;
        int row = g * HC + j;
        g_WcT[i] = (k < DC) ? Wcih[(size_t)row * DC + k]
                            : Wchh[(size_t)row * HC + (k - DC)];
        return;
    }
    i -= N_WC;
    if (i < N_WT) {
        int k = (int)(i >> 6), t = (int)(i & 63);
        g_WtT[i] = Wtag[(size_t)t * HW + k];
        return;
    }
    i -= N_WT;
    if (i < N_WIN) {
        int s = (int)(i >> 8), d = (int)(i & 255);
        g_win[(size_t)s * HW + d] = wemb[(size_t)wixs[s] * DW + d];
        return;
    }
    i -= N_WIN;
    if (i < N_HPK) {
        // both parities: {h=0, tag=0}; parity-0 tag 0 == expected tag at step 0
        g_hpk[i] = 0ull;
    }
}

// ================= kernel 1: char LSTM (16 words / CTA) =================
__global__ __launch_bounds__(256, 1)
void k_char(const int* __restrict__ cix, const int* __restrict__ clen,
            const float* __restrict__ cemb,
            const float* __restrict__ bcih, const float* __restrict__ bchh)
{
    __shared__ __align__(16) float xT[DC * 18];   // [k][word], padded row 18
    __shared__ __align__(16) float hT[HC * 18];
    const int j  = threadIdx.x;                   // hidden unit
    const int w0 = blockIdx.x * 16;

    float bi[4];
#pragma unroll
    for (int g = 0; g < 4; g++) bi[g] = bcih[g * HC + j] + bchh[g * HC + j];

    int len[16];
#pragma unroll
    for (int w = 0; w < 16; w++) len[w] = clen[w0 + w];

    float c[16];
#pragma unroll
    for (int w = 0; w < 16; w++) c[w] = 0.0f;

    for (int i = j; i < HC * 18; i += 256) hT[i] = 0.0f;
    // stage x for t=0
    for (int i = j; i < 1024; i += 256) {
        int w = i >> 6, k = i & 63;
        xT[k * 18 + w] = cemb[(size_t)cix[(w0 + w) * LMAX + 0] * DC + k];
    }

    for (int t = 0; t < LMAX; t++) {
        __syncthreads();   // hT/xT writes visible

        unsigned long long acc[4][8];
#pragma unroll
        for (int g = 0; g < 4; g++) {
            unsigned long long bp = pk2(bi[g], bi[g]);
#pragma unroll
            for (int p = 0; p < 8; p++) acc[g][p] = bp;
        }

        // K over x (0..63)
        for (int k = 0; k < DC; k++) {
            float4 wv = ((const float4*)g_WcT)[k * HC + j];
            const unsigned long long* xr = (const unsigned long long*)(xT + k * 18);
            unsigned long long wp0 = pk2(wv.x, wv.x), wp1 = pk2(wv.y, wv.y);
            unsigned long long wp2 = pk2(wv.z, wv.z), wp3 = pk2(wv.w, wv.w);
#pragma unroll
            for (int p = 0; p < 8; p++) {
                unsigned long long xp = xr[p];
                fma2(acc[0][p], wp0, xp); fma2(acc[1][p], wp1, xp);
                fma2(acc[2][p], wp2, xp); fma2(acc[3][p], wp3, xp);
            }
        }
        // K over h (0..255)
        for (int k = 0; k < HC; k++) {
            float4 wv = ((const float4*)g_WcT)[(DC + k) * HC + j];
            const unsigned long long* xr = (const unsigned long long*)(hT + k * 18);
            unsigned long long wp0 = pk2(wv.x, wv.x), wp1 = pk2(wv.y, wv.y);
            unsigned long long wp2 = pk2(wv.z, wv.z), wp3 = pk2(wv.w, wv.w);
#pragma unroll
            for (int p = 0; p < 8; p++) {
                unsigned long long xp = xr[p];
                fma2(acc[0][p], wp0, xp); fma2(acc[1][p], wp1, xp);
                fma2(acc[2][p], wp2, xp); fma2(acc[3][p], wp3, xp);
            }
        }

        __syncthreads();   // all reads of hT/xT done

        // epilogue: update c / h (frozen past word length)
#pragma unroll
        for (int p = 0; p < 8; p++) {
            float i0, i1, f0, f1, gg0, gg1, o0, o1;
            up2(acc[0][p], i0, i1); up2(acc[1][p], f0, f1);
            up2(acc[2][p], gg0, gg1); up2(acc[3][p], o0, o1);
            int w = 2 * p;
            if (t < len[w]) {
                c[w] = sigf(f0) * c[w] + sigf(i0) * tanhf_(gg0);
                hT[j * 18 + w] = sigf(o0) * tanhf_(c[w]);
            }
            w = 2 * p + 1;
            if (t < len[w]) {
                c[w] = sigf(f1) * c[w] + sigf(i1) * tanhf_(gg1);
                hT[j * 18 + w] = sigf(o1) * tanhf_(c[w]);
            }
        }
        // stage x for next step
        if (t + 1 < LMAX) {
            for (int i = j; i < 1024; i += 256) {
                int w = i >> 6, k = i & 63;
                xT[k * 18 + w] = cemb[(size_t)cix[(w0 + w) * LMAX + (t + 1)] * DC + k];
            }
        }
    }
    __syncthreads();
#pragma unroll
    for (int w = 0; w < 16; w++)
        g_win[(size_t)(w0 + w) * HW + DW + j] = hT[j * 18 + w];
}

// ================= kernel 2: word-input GEMM: Gw = win @ Wwih^T + bw =================
__global__ __launch_bounds__(256, 1)
void k_gemm(const float* __restrict__ Wwih,
            const float* __restrict__ bwih, const float* __restrict__ bwhh)
{
    __shared__ __align__(16) float As[32 * 132];
    __shared__ __align__(16) float Bs[32 * 132];
    const int tid = threadIdx.x;
    const int tx = tid & 15, ty = tid >> 4;
    const int sbase = blockIdx.y * 128, rbase = blockIdx.x * 128;

    unsigned long long acc[8][4];
#pragma unroll
    for (int i = 0; i < 8; i++)
#pragma unroll
        for (int p = 0; p < 4; p++) acc[i][p] = pk2(0.0f, 0.0f);

    for (int kt = 0; kt < HW; kt += 32) {
        __syncthreads();
#pragma unroll
        for (int q = 0; q < 4; q++) {
            int idx = tid + 256 * q;          // 0..1023
            int sr = idx >> 3, f = idx & 7;
            float4 av = *(const float4*)(g_win + (size_t)(sbase + sr) * HW + kt + f * 4);
            As[(f * 4 + 0) * 132 + sr] = av.x;
            As[(f * 4 + 1) * 132 + sr] = av.y;
            As[(f * 4 + 2) * 132 + sr] = av.z;
            As[(f * 4 + 3) * 132 + sr] = av.w;
            float4 bv = *(const float4*)(Wwih + (size_t)(rbase + sr) * HW + kt + f * 4);
            Bs[(f * 4 + 0) * 132 + sr] = bv.x;
            Bs[(f * 4 + 1) * 132 + sr] = bv.y;
            Bs[(f * 4 + 2) * 132 + sr] = bv.z;
            Bs[(f * 4 + 3) * 132 + sr] = bv.w;
        }
        __syncthreads();
#pragma unroll
        for (int k = 0; k < 32; k++) {
            const float* ar = As + k * 132 + ty * 8;
            float4 a0 = *(const float4*)ar;
            float4 a1 = *(const float4*)(ar + 4);
            const unsigned long long* br = (const unsigned long long*)(Bs + k * 132 + tx * 8);
            unsigned long long b0 = br[0], b1 = br[1], b2 = br[2], b3 = br[3];
            float a[8] = {a0.x, a0.y, a0.z, a0.w, a1.x, a1.y, a1.z, a1.w};
#pragma unroll
            for (int i = 0; i < 8; i++) {
                unsigned long long ap = pk2(a[i], a[i]);
                fma2(acc[i][0], ap, b0); fma2(acc[i][1], ap, b1);
                fma2(acc[i][2], ap, b2); fma2(acc[i][3], ap, b3);
            }
        }
    }
#pragma unroll
    for (int i = 0; i < 8; i++) {
        int srow = sbase + ty * 8 + i;
#pragma unroll
        for (int pq = 0; pq < 4; pq++) {
            float lo, hi; up2(acc[i][pq], lo, hi);
            int rcol = rbase + tx * 8 + 2 * pq;
            lo += bwih[rcol] + bwhh[rcol];
            hi += bwih[rcol + 1] + bwhh[rcol + 1];
            *(float2*)(g_Gw + (size_t)srow * GW + rcol) = make_float2(lo, hi);
        }
    }
}

// ================= kernel 3: word LSTM (persistent, 64 CTAs, Whh in registers) ===========
// Sync protocol: tagged 64-bit words {h, step}, double-buffered by parity.
// No fences, no flags, no volatile — one L2 round-trip of dataflow per step.
__global__ __launch_bounds__(256, 1)
void k_word(const float* __restrict__ Whh)
{
    __shared__ __align__(16) float sh[HW];
    const int tid = threadIdx.x, b = blockIdx.x;
    const int p = tid & 7;             // part of a row (8 parts x 64 weights)
    const int r_local = tid >> 3;      // 0..31
    const int j_local = r_local >> 2;  // 0..7  (unit within CTA; warp == unit)
    const int gate = r_local & 3;      // 0..3 (i,f,g,o)
    const int lane = tid & 31;
    const int grow = gate * HW + b * 8 + j_local;
    const int jglob = b * 8 + j_local;

    // 64 weights per thread in registers, packed as f32x2 pairs
    unsigned long long wpk[32];
    {
        const float4* wsrc = (const float4*)(Whh + (size_t)grow * HW + p * 64);
#pragma unroll
        for (int q = 0; q < 16; q++) {
            float4 v = wsrc[q];
            wpk[2 * q]     = pk2(v.x, v.y);
            wpk[2 * q + 1] = pk2(v.z, v.w);
        }
    }

    float cst = 0.0f;   // cell state (valid on lane 0 of each warp)
    float gw_cur = (p == 0) ? __ldcs(&g_Gw[grow]) : 0.0f;   // ih-gate for step 0

    for (int s = 0; s < S_; s++) {
        // prefetch next step's ih-gate (DRAM latency hidden under this step)
        float gw_next = 0.0f;
        if (p == 0 && s + 1 < S_)
            gw_next = __ldcs(&g_Gw[(size_t)(s + 1) * GW + grow]);

        // stage h_s: each thread polls its 2 tagged words until tag == s
        {
            const unsigned long long* src = g_hpk + (s & 1) * HW;
            unsigned long long v0 = ldtag(src + tid);
            unsigned long long v1 = ldtag(src + tid + 256);
            while ((unsigned)(v0 >> 32) != (unsigned)s) v0 = ldtag(src + tid);
            while ((unsigned)(v1 >> 32) != (unsigned)s) v1 = ldtag(src + tid + 256);
            sh[tid]       = __uint_as_float((unsigned)v0);
            sh[tid + 256] = __uint_as_float((unsigned)v1);
        }
        __syncthreads();

        // dot product over my 64-wide slice
        unsigned long long a0 = pk2(0.f, 0.f), a1 = a0, a2 = a0, a3 = a0;
        const ulonglong2* hr2 = (const ulonglong2*)(sh + p * 64);
#pragma unroll
        for (int q = 0; q < 16; q += 2) {
            ulonglong2 h0 = hr2[q];
            ulonglong2 h1 = hr2[q + 1];
            fma2(a0, wpk[2 * q],     h0.x);
            fma2(a1, wpk[2 * q + 1], h0.y);
            fma2(a2, wpk[2 * q + 2], h1.x);
            fma2(a3, wpk[2 * q + 3], h1.y);
        }
        float l0, h0f, l2, h2f;
        up2(a0, l0, h0f); up2(a2, l2, h2f);
        float sum;
        {
            float s01, s23;
            up2(a1, s01, s23);          // reuse regs: a1 parts
            float x0, x1; up2(a3, x0, x1);
            sum = ((l0 + h0f) + (s01 + s23)) + ((l2 + h2f) + (x0 + x1));
        }
        // reduce across the 8 p-lanes of this (unit,gate) row
        sum += __shfl_down_sync(0xffffffffu, sum, 4);
        sum += __shfl_down_sync(0xffffffffu, sum, 2);
        sum += __shfl_down_sync(0xffffffffu, sum, 1);

        // activations computed in parallel on lanes 0,8,16,24 (gates i,f,g,o)
        float act = 0.0f;
        if (p == 0) {
            float x = sum + gw_cur;
            act = (gate == 2) ? tanhf_(x) : sigf(x);
        }
        float fa = __shfl_sync(0xffffffffu, act, 8);
        float ga = __shfl_sync(0xffffffffu, act, 16);
        float oa = __shfl_sync(0xffffffffu, act, 24);

        if (lane == 0) {
            cst = fa * cst + act * ga;          // act = sig(i) on lane 0
            float h = oa * tanhf_(cst);
            g_hs[(size_t)s * HW + jglob] = h;
            sttag(g_hpk + ((s + 1) & 1) * HW + jglob, pktag(h, (unsigned)(s + 1)));
        }
        gw_cur = gw_next;
        // no trailing __syncthreads: next poll can only pass after all warps
        // everywhere stored tag s+1, which happens after their sh reads.
    }
}

// ================= kernel 4: tag projection + log-softmax =================
__global__ __launch_bounds__(64, 8)
void k_tag(const float* __restrict__ btag, float* __restrict__ out)
{
    __shared__ __align__(16) float sh[HW];
    __shared__ float red[2];
    const int s = blockIdx.x, t = threadIdx.x;

#pragma unroll
    for (int q = 0; q < 8; q++)
        sh[t + q * 64] = g_hs[(size_t)s * HW + t + q * 64];
    __syncthreads();

    float acc = btag[t];
#pragma unroll 8
    for (int k = 0; k < HW; k++) acc += sh[k] * g_WtT[k * TT + t];

    // log-softmax over 64 lanes (2 warps)
    float m = acc;
#pragma unroll
    for (int d = 16; d > 0; d >>= 1) m = fmaxf(m, __shfl_xor_sync(0xffffffffu, m, d));
    if ((t & 31) == 0) red[t >> 5] = m;
    __syncthreads();
    m = fmaxf(red[0], red[1]);
    __syncthreads();

    float e = expf(acc - m);
    float ss = e;
#pragma unroll
    for (int d = 16; d > 0; d >>= 1) ss += __shfl_xor_sync(0xffffffffu, ss, d);
    if ((t & 31) == 0) red[t >> 5] = ss;
    __syncthreads();
    ss = red[0] + red[1];

    out[s * TT + t] = acc - m - logf(ss);
}

// ================= launch =================
extern "C" void kernel_launch(void* const* d_in, const int* in_sizes, int n_in,
                              void* d_out, int out_size)
{
    const int*   word_ixs = (const int*)d_in[0];
    const int*   char_ixs = (const int*)d_in[1];
    const int*   char_len = (const int*)d_in[2];
    const float* word_emb = (const float*)d_in[3];
    const float* char_emb = (const float*)d_in[4];
    const float* Wc_ih    = (const float*)d_in[5];
    const float* Wc_hh    = (const float*)d_in[6];
    const float* bc_ih    = (const float*)d_in[7];
    const float* bc_hh    = (const float*)d_in[8];
    const float* Ww_ih    = (const float*)d_in[9];
    const float* Ww_hh    = (const float*)d_in[10];
    const float* bw_ih    = (const float*)d_in[11];
    const float* bw_hh    = (const float*)d_in[12];
    const float* W_tag    = (const float*)d_in[13];
    const float* b_tag    = (const float*)d_in[14];
    float* out = (float*)d_out;

    k_prep<<<(N_PREP + 255) / 256, 256>>>(Wc_ih, Wc_hh, W_tag, word_emb, word_ixs);
    k_char<<<S_ / 16, 256>>>(char_ixs, char_len, char_emb, bc_ih, bc_hh);
    k_gemm<<<dim3(GW / 128, S_ / 128), 256>>>(Ww_ih, bw_ih, bw_hh);
    k_word<<<WCTA, 256>>>(Ww_hh);
    k_tag<<<S_, 64>>>(b_tag, out);
}